// round 14
// baseline (speedup 1.0000x reference)
#include <cuda_runtime.h>
#include <cuda_bf16.h>
#include <cuda_fp16.h>
#include <math.h>
#include <stdint.h>

#define Nn 20000
#define Tt 256
#define Ee 320000
#define Gg 64
#define CT 8
#define CP 16
#define EMB 768
#define OUTC 4
#define FIN 512
#define BN_EPS 1e-5f

// ---------------- scratch (device globals, no allocation) ----------------
__device__ __align__(16) __half g_h0h[(size_t)Nn * FIN];
__device__ __align__(16) __half g_agg1h[(size_t)Nn * FIN];
__device__ __align__(16) __half g_zh[(size_t)Nn * EMB];
__device__ __align__(16) __half g_h1h[(size_t)Nn * EMB];
__device__ __align__(16) __half g_agg2h[(size_t)Nn * EMB];
__device__ __align__(16) __half g_h2h[(size_t)Nn * EMB];
__device__ float g_sums[Gg * EMB];
__device__ float g_cnt[Gg];

// CSR scratch
__device__ int g_deg[Nn];
__device__ int g_off[Nn + 4];
__device__ int g_pos[Nn];
__device__ int g_elist[Ee];

// packed fp16x2 weight buffer: layout [K/2][M] uint32 (pair along k)
#define WO1 0
#define WO2 196608
#define WO3 491520
#define WO4 786432
#define WTOT 1081344
__device__ uint32_t g_wh[WTOT];

// ---------------- fused temporal conv + BN + pool (fp16 out) ----------------
__global__ void __launch_bounds__(256) conv_kernel(
    const float* __restrict__ x,
    const float* __restrict__ w0,
    const float* __restrict__ g0, const float* __restrict__ b0,
    const float* __restrict__ m0, const float* __restrict__ v0,
    const float* __restrict__ w1,
    const float* __restrict__ w2,
    const float* __restrict__ g2, const float* __restrict__ b2,
    const float* __restrict__ m2, const float* __restrict__ v2,
    __half* __restrict__ hout)
{
    __shared__ float xs[256];
    __shared__ float w0s[33 * 8];
    __shared__ float w1s[21 * 8];
    __shared__ float w2s[8 * 16];
    __shared__ float sc0[8], sh0[8], sc2[16], sh2[16];
    __shared__ float s1s[8][264];

    const int t = threadIdx.x;
    const int n = blockIdx.x;

    xs[t] = x[(size_t)n * Tt + t];
    for (int i = t; i < 33 * 8; i += 256) w0s[i] = w0[i];
    if (t < 21 * 8) w1s[t] = w1[t];
    if (t < 8 * 16) w2s[t] = w2[t];
    if (t < 8)  { float s = g0[t] * rsqrtf(v0[t] + BN_EPS); sc0[t] = s; sh0[t] = b0[t] - m0[t] * s; }
    if (t < 16) { float s = g2[t] * rsqrtf(v2[t] + BN_EPS); sc2[t] = s; sh2[t] = b2[t] - m2[t] * s; }
    __syncthreads();

    float acc[8];
#pragma unroll
    for (int c = 0; c < 8; c++) acc[c] = 0.f;
#pragma unroll
    for (int w = 0; w < 33; w++) {
        int tt = t + w - 16;
        float xv = (tt >= 0 && tt < 256) ? xs[tt] : 0.f;
#pragma unroll
        for (int c = 0; c < 8; c++) acc[c] += xv * w0s[w * 8 + c];
    }
#pragma unroll
    for (int c = 0; c < 8; c++) s1s[c][t] = acc[c] * sc0[c] + sh0[c];
    __syncthreads();

    float s2[8];
#pragma unroll
    for (int c = 0; c < 8; c++) {
        float a = 0.f;
#pragma unroll
        for (int w = 0; w < 21; w++) {
            int tt = t + w - 10;
            float xv = (tt >= 0 && tt < 256) ? s1s[c][tt] : 0.f;
            a += xv * w1s[w * 8 + c];
        }
        s2[c] = fmaxf(a, 0.f);
    }

    const int lane = t & 31;
#pragma unroll
    for (int o = 0; o < 16; o++) {
        float a = 0.f;
#pragma unroll
        for (int c = 0; c < 8; c++) a += s2[c] * w2s[c * 16 + o];
        a = fmaxf(a * sc2[o] + sh2[o], 0.f);
        a += __shfl_xor_sync(0xffffffffu, a, 1);
        a += __shfl_xor_sync(0xffffffffu, a, 2);
        a += __shfl_xor_sync(0xffffffffu, a, 4);
        if ((lane & 7) == 0)
            hout[(size_t)n * FIN + (t >> 3) * 16 + o] = __float2half(a * 0.125f);
    }
}

// ---------------- utility kernels ----------------
__global__ void zero_kernel(float4* __restrict__ p, int n4)
{
    int i = blockIdx.x * blockDim.x + threadIdx.x;
    int stride = gridDim.x * blockDim.x;
    float4 z = make_float4(0.f, 0.f, 0.f, 0.f);
    for (; i < n4; i += stride) p[i] = z;
}

// ---------------- weight prep: all 4 fp32 [K][M] -> packed fp16x2 [K/2][M] ----
__global__ void __launch_bounds__(256) wprep_all_kernel(
    const float* __restrict__ w1, const float* __restrict__ w2,
    const float* __restrict__ w3, const float* __restrict__ w4,
    uint32_t* __restrict__ Wh)
{
    int idx = blockIdx.x * blockDim.x + threadIdx.x;
    if (idx >= WTOT) return;
    const float* W;
    int local;
    if (idx < WO2)      { W = w1; local = idx; }
    else if (idx < WO3) { W = w2; local = idx - WO2; }
    else if (idx < WO4) { W = w3; local = idx - WO3; }
    else                { W = w4; local = idx - WO4; }
    int kp = local / EMB, n = local - kp * EMB;
    float f0 = W[(size_t)(2 * kp) * EMB + n];
    float f1 = W[(size_t)(2 * kp + 1) * EMB + n];
    __half2 h = __floats2half2_rn(f0, f1);
    Wh[idx] = *(uint32_t*)&h;
}

// ---------------- CSR build ----------------
__global__ void count_kernel(const int* __restrict__ ei, int* __restrict__ deg)
{
    int e = blockIdx.x * blockDim.x + threadIdx.x;
    if (e < Ee) atomicAdd(&deg[__ldg(ei + Ee + e)], 1);
}

// thread-coarsened single-block exclusive scan: each thread handles CH elems
__global__ void __launch_bounds__(1024) scan_kernel(
    const int* __restrict__ deg, int* __restrict__ off, int* __restrict__ pos, int n)
{
    const int CH = 20;  // 1024 * 20 >= 20000
    __shared__ int wsum[32];
    const int tid = threadIdx.x, lane = tid & 31, wid = tid >> 5;
    const int base = tid * CH;

    int vals[CH];
    int s = 0;
#pragma unroll
    for (int i = 0; i < CH; i++) {
        int idx = base + i;
        int v = (idx < n) ? deg[idx] : 0;
        vals[i] = s;
        s += v;
    }
    // block exclusive scan of per-thread totals
    int x = s;
#pragma unroll
    for (int d = 1; d < 32; d <<= 1) {
        int y = __shfl_up_sync(0xffffffffu, x, d);
        if (lane >= d) x += y;
    }
    if (lane == 31) wsum[wid] = x;
    __syncthreads();
    if (wid == 0) {
        int w = wsum[lane];
#pragma unroll
        for (int d = 1; d < 32; d <<= 1) {
            int y = __shfl_up_sync(0xffffffffu, w, d);
            if (lane >= d) w += y;
        }
        wsum[lane] = w;
    }
    __syncthreads();
    int tbase = x - s + ((wid == 0) ? 0 : wsum[wid - 1]);
#pragma unroll
    for (int i = 0; i < CH; i++) {
        int idx = base + i;
        if (idx < n) {
            int e = tbase + vals[i];
            off[idx] = e;
            pos[idx] = e;
        }
    }
    if (tid == 1023) off[n] = tbase + s;
}

__global__ void fill_kernel(const int* __restrict__ ei,
                            int* __restrict__ pos, int* __restrict__ elist)
{
    int e = blockIdx.x * blockDim.x + threadIdx.x;
    if (e < Ee) {
        int d = __ldg(ei + Ee + e);
        int p = atomicAdd(&pos[d], 1);
        elist[p] = __ldg(ei + e);
    }
}

// ---------------- CSR gather (fp16 in/out, fp32 accumulate, 4-way MLP) --------
template <int F>
__global__ void __launch_bounds__(F / 8) gather_kernel(
    const int* __restrict__ off, const int* __restrict__ elist,
    const __half* __restrict__ h, __half* __restrict__ agg)
{
    const int n = blockIdx.x;
    const int f = threadIdx.x;
    float a[8];
    {
        uint4 u = __ldg((const uint4*)(h + (size_t)n * F) + f);
        float2 p0 = __half22float2(*(__half2*)&u.x);
        float2 p1 = __half22float2(*(__half2*)&u.y);
        float2 p2 = __half22float2(*(__half2*)&u.z);
        float2 p3 = __half22float2(*(__half2*)&u.w);
        a[0] = p0.x; a[1] = p0.y; a[2] = p1.x; a[3] = p1.y;
        a[4] = p2.x; a[5] = p2.y; a[6] = p3.x; a[7] = p3.y;
    }
    int s = __ldg(off + n);
    const int e = __ldg(off + n + 1);
#define ACCUM(u) do { \
        float2 q; \
        q = __half22float2(*(__half2*)&(u).x); a[0] += q.x; a[1] += q.y; \
        q = __half22float2(*(__half2*)&(u).y); a[2] += q.x; a[3] += q.y; \
        q = __half22float2(*(__half2*)&(u).z); a[4] += q.x; a[5] += q.y; \
        q = __half22float2(*(__half2*)&(u).w); a[6] += q.x; a[7] += q.y; \
    } while (0)
    for (; s + 3 < e; s += 4) {
        int s0 = __ldg(elist + s);
        int s1 = __ldg(elist + s + 1);
        int s2 = __ldg(elist + s + 2);
        int s3 = __ldg(elist + s + 3);
        uint4 u0 = __ldg((const uint4*)(h + (size_t)s0 * F) + f);
        uint4 u1 = __ldg((const uint4*)(h + (size_t)s1 * F) + f);
        uint4 u2 = __ldg((const uint4*)(h + (size_t)s2 * F) + f);
        uint4 u3 = __ldg((const uint4*)(h + (size_t)s3 * F) + f);
        ACCUM(u0); ACCUM(u1); ACCUM(u2); ACCUM(u3);
    }
    for (; s < e; s++) {
        int s0 = __ldg(elist + s);
        uint4 u0 = __ldg((const uint4*)(h + (size_t)s0 * F) + f);
        ACCUM(u0);
    }
#undef ACCUM
    uint4 o;
    __half2 h0 = __floats2half2_rn(a[0], a[1]);
    __half2 h1 = __floats2half2_rn(a[2], a[3]);
    __half2 h2 = __floats2half2_rn(a[4], a[5]);
    __half2 h3 = __floats2half2_rn(a[6], a[7]);
    o.x = *(uint32_t*)&h0; o.y = *(uint32_t*)&h1;
    o.z = *(uint32_t*)&h2; o.w = *(uint32_t*)&h3;
    *((uint4*)(agg + (size_t)n * F) + f) = o;
}

// ---------------- fp16 GEMM: 256x128 block, 64x64 warp tiles, cp.async x3 ----
#define BM 256
#define BN 128
#define BK 32
#define KP 16
#define AS_STRIDE 20
#define BS_STRIDE 136
#define NSTAGE 3
#define AS_ELEMS (BM * AS_STRIDE)
#define BS_ELEMS (KP * BS_STRIDE)
#define GEMM_SMEM_BYTES ((NSTAGE * (AS_ELEMS + BS_ELEMS)) * 4)

__device__ __forceinline__ void cp_async16(uint32_t dst, const void* src, int sz)
{
    asm volatile("cp.async.cg.shared.global [%0], [%1], 16, %2;"
                 :: "r"(dst), "l"(src), "r"(sz));
}
__device__ __forceinline__ void cp_commit()
{
    asm volatile("cp.async.commit_group;");
}

__device__ __forceinline__ void mma_fp16(
    float* d, const uint32_t* a, uint32_t b0, uint32_t b1)
{
    asm volatile(
        "mma.sync.aligned.m16n8k16.row.col.f32.f16.f16.f32 "
        "{%0,%1,%2,%3}, {%4,%5,%6,%7}, {%8,%9}, {%0,%1,%2,%3};"
        : "+f"(d[0]), "+f"(d[1]), "+f"(d[2]), "+f"(d[3])
        : "r"(a[0]), "r"(a[1]), "r"(a[2]), "r"(a[3]), "r"(b0), "r"(b1));
}

__global__ void __launch_bounds__(256, 1) gemm_fp16_kernel(
    const __half* __restrict__ A,
    const uint32_t* __restrict__ Bh,
    const float* __restrict__ bias,
    __half* __restrict__ C, int Nrows, int K, int M, int doRelu)
{
    extern __shared__ uint32_t smem[];
    uint32_t* AsBase = smem;
    uint32_t* BsBase = smem + NSTAGE * AS_ELEMS;

    const int tid = threadIdx.x;
    const int lane = tid & 31;
    const int warp = tid >> 5;
    const int warp_m = warp & 3;   // 4 -> m offset warp_m*64
    const int warp_n = warp >> 2;  // 2 -> n offset warp_n*64
    const int rowBase = blockIdx.y * BM;
    const int colBase = blockIdx.x * BN;

    const int r0 = tid >> 2;      // 0..63; rows r0 + 64h, h=0..3
    const int c4 = tid & 3;       // uint4 chunk in k-tile
    const int kp0 = tid >> 5;     // 0..7; kpairs kp0, kp0+8
    const int n4 = tid & 31;      // 0..31

    // A global srcs (4 rows per thread), clamped with sz=0 masking
    const __half* aSrc[4];
    int sz[4];
#pragma unroll
    for (int h = 0; h < 4; h++) {
        int r = rowBase + r0 + h * 64;
        sz[h] = (r < Nrows) ? 16 : 0;
        if (r >= Nrows) r = Nrows - 1;
        aSrc[h] = A + (size_t)r * K + c4 * 8;
    }
    const uint32_t* bSrc0 = Bh + (size_t)kp0 * M + colBase + n4 * 4;
    const uint32_t* bSrc1 = Bh + (size_t)(kp0 + 8) * M + colBase + n4 * 4;

    // smem stage bases + fixed offsets (bytes)
    uint32_t abase[NSTAGE], bbase[NSTAGE];
#pragma unroll
    for (int b = 0; b < NSTAGE; b++) {
        abase[b] = (uint32_t)__cvta_generic_to_shared(AsBase + b * AS_ELEMS);
        bbase[b] = (uint32_t)__cvta_generic_to_shared(BsBase + b * BS_ELEMS);
    }
    uint32_t aoff[4];
#pragma unroll
    for (int h = 0; h < 4; h++)
        aoff[h] = ((r0 + h * 64) * AS_STRIDE + c4 * 4) * 4;
    const uint32_t boff0 = (kp0 * BS_STRIDE + n4 * 4) * 4;
    const uint32_t boff1 = ((kp0 + 8) * BS_STRIDE + n4 * 4) * 4;

    float acc[4][8][4];
#pragma unroll
    for (int i = 0; i < 4; i++)
#pragma unroll
        for (int j = 0; j < 8; j++)
#pragma unroll
            for (int r = 0; r < 4; r++) acc[i][j][r] = 0.f;

    const int nsteps = K / BK;

#define ISSUE(s) do { \
        int _b = (s) % NSTAGE; \
        cp_async16(abase[_b] + aoff[0], aSrc[0] + (size_t)(s) * BK, sz[0]); \
        cp_async16(abase[_b] + aoff[1], aSrc[1] + (size_t)(s) * BK, sz[1]); \
        cp_async16(abase[_b] + aoff[2], aSrc[2] + (size_t)(s) * BK, sz[2]); \
        cp_async16(abase[_b] + aoff[3], aSrc[3] + (size_t)(s) * BK, sz[3]); \
        cp_async16(bbase[_b] + boff0, bSrc0 + (size_t)(s) * KP * M, 16); \
        cp_async16(bbase[_b] + boff1, bSrc1 + (size_t)(s) * KP * M, 16); \
        cp_commit(); \
    } while (0)

    ISSUE(0);
    if (nsteps > 1) ISSUE(1);

    for (int s = 0; s < nsteps; s++) {
        if (s + 1 < nsteps) asm volatile("cp.async.wait_group 1;");
        else                asm volatile("cp.async.wait_group 0;");
        __syncthreads();
        if (s + 2 < nsteps) ISSUE(s + 2);

        const uint32_t* As = AsBase + (s % NSTAGE) * AS_ELEMS;
        const uint32_t* Bs = BsBase + (s % NSTAGE) * BS_ELEMS;

#pragma unroll
        for (int step = 0; step < 2; step++) {
            const int koff = step * 8;
            uint32_t a[4][4];
#pragma unroll
            for (int i = 0; i < 4; i++) {
                int mr = warp_m * 64 + i * 16 + (lane >> 2);
                int kc = koff + (lane & 3);
                a[i][0] = As[mr * AS_STRIDE + kc];
                a[i][1] = As[(mr + 8) * AS_STRIDE + kc];
                a[i][2] = As[mr * AS_STRIDE + kc + 4];
                a[i][3] = As[(mr + 8) * AS_STRIDE + kc + 4];
            }
#pragma unroll
            for (int j = 0; j < 8; j++) {
                int kb = koff + (lane & 3);
                int nb = warp_n * 64 + j * 8 + (lane >> 2);
                uint32_t b0 = Bs[kb * BS_STRIDE + nb];
                uint32_t b1 = Bs[(kb + 4) * BS_STRIDE + nb];
#pragma unroll
                for (int i = 0; i < 4; i++) {
                    mma_fp16(acc[i][j], a[i], b0, b1);
                }
            }
        }
    }
#undef ISSUE

    // ---- epilogue: bias + relu, pack half2 stores ----
#pragma unroll
    for (int i = 0; i < 4; i++) {
        int r = rowBase + warp_m * 64 + i * 16 + (lane >> 2);
#pragma unroll
        for (int j = 0; j < 8; j++) {
            int c0 = colBase + warp_n * 64 + j * 8 + (lane & 3) * 2;
            float b0v = bias[c0];
            float b1v = bias[c0 + 1];
            float v0 = acc[i][j][0] + b0v;
            float v1 = acc[i][j][1] + b1v;
            float v2 = acc[i][j][2] + b0v;
            float v3 = acc[i][j][3] + b1v;
            if (doRelu) {
                v0 = fmaxf(v0, 0.f); v1 = fmaxf(v1, 0.f);
                v2 = fmaxf(v2, 0.f); v3 = fmaxf(v3, 0.f);
            }
            if (r < Nrows) {
                __half2 p = __floats2half2_rn(v0, v1);
                *(uint32_t*)(C + (size_t)r * M + c0) = *(uint32_t*)&p;
            }
            if (r + 8 < Nrows) {
                __half2 p = __floats2half2_rn(v2, v3);
                *(uint32_t*)(C + (size_t)(r + 8) * M + c0) = *(uint32_t*)&p;
            }
        }
    }
}

// ---------------- graph mean-pool: sums/counts (fp16 in, red.v4) -------------
__global__ void __launch_bounds__(192) pool_kernel(
    const int* __restrict__ batch, const __half* __restrict__ h,
    float* __restrict__ sums, float* __restrict__ cnt)
{
    const int n = blockIdx.x;
    const int b = __ldg(batch + n);
    const int f = threadIdx.x;
    uint2 u = __ldg((const uint2*)(h + (size_t)n * EMB) + f);
    float2 p0 = __half22float2(*(__half2*)&u.x);
    float2 p1 = __half22float2(*(__half2*)&u.y);
    float* s = sums + (size_t)b * EMB + f * 4;
    asm volatile("red.global.add.v4.f32 [%0], {%1,%2,%3,%4};"
                 :: "l"(s), "f"(p0.x), "f"(p0.y), "f"(p1.x), "f"(p1.y) : "memory");
    if (f == 0) atomicAdd(&cnt[b], 1.0f);
}

// ---------------- head: mean, dense, log_softmax ----------------
__global__ void __launch_bounds__(192) head_kernel(
    const float* __restrict__ sums, const float* __restrict__ cnt,
    const float* __restrict__ W, const float* __restrict__ bias,
    float* __restrict__ out)
{
    __shared__ float red[192][4];
    const int g = blockIdx.x;
    const int t = threadIdx.x;
    const float c = fmaxf(cnt[g], 1.f);
    float4 p = *(const float4*)(sums + (size_t)g * EMB + t * 4);
    const float inv = 1.f / c;
    p.x *= inv; p.y *= inv; p.z *= inv; p.w *= inv;
    const int f = t * 4;
#pragma unroll
    for (int o = 0; o < 4; o++) {
        red[t][o] = p.x * W[(f + 0) * 4 + o] + p.y * W[(f + 1) * 4 + o] +
                    p.z * W[(f + 2) * 4 + o] + p.w * W[(f + 3) * 4 + o];
    }
    __syncthreads();
    if (t == 0) {
        float l[4];
#pragma unroll
        for (int o = 0; o < 4; o++) {
            float s = bias[o];
            for (int i = 0; i < 192; i++) s += red[i][o];
            l[o] = s;
        }
        float m = fmaxf(fmaxf(l[0], l[1]), fmaxf(l[2], l[3]));
        float se = expf(l[0] - m) + expf(l[1] - m) + expf(l[2] - m) + expf(l[3] - m);
        float lse = m + logf(se);
#pragma unroll
        for (int o = 0; o < 4; o++) out[g * 4 + o] = l[o] - lse;
    }
}

// ---------------- launch ----------------
extern "C" void kernel_launch(void* const* d_in, const int* in_sizes, int n_in,
                              void* d_out, int out_size)
{
    const float* x       = (const float*)d_in[0];
    const int*   ei      = (const int*)d_in[1];
    const int*   batch   = (const int*)d_in[2];
    const float* conv0_w = (const float*)d_in[3];
    const float* bn0_g   = (const float*)d_in[4];
    const float* bn0_b   = (const float*)d_in[5];
    const float* bn0_m   = (const float*)d_in[6];
    const float* bn0_v   = (const float*)d_in[7];
    const float* conv1_w = (const float*)d_in[8];
    const float* conv2_w = (const float*)d_in[9];
    const float* bn2_g   = (const float*)d_in[10];
    const float* bn2_b   = (const float*)d_in[11];
    const float* bn2_m   = (const float*)d_in[12];
    const float* bn2_v   = (const float*)d_in[13];
    const float* g1w1    = (const float*)d_in[14];
    const float* g1b1    = (const float*)d_in[15];
    const float* g1w2    = (const float*)d_in[16];
    const float* g1b2    = (const float*)d_in[17];
    const float* g2w1    = (const float*)d_in[18];
    const float* g2b1    = (const float*)d_in[19];
    const float* g2w2    = (const float*)d_in[20];
    const float* g2b2    = (const float*)d_in[21];
    const float* dW      = (const float*)d_in[22];
    const float* dB      = (const float*)d_in[23];
    float* out = (float*)d_out;

    __half *p_h0, *p_agg1, *p_z, *p_h1, *p_agg2, *p_h2;
    float *p_sums, *p_cnt;
    uint32_t *p_wh;
    int *p_deg, *p_off, *p_pos, *p_elist;
    cudaGetSymbolAddress((void**)&p_h0,   g_h0h);
    cudaGetSymbolAddress((void**)&p_agg1, g_agg1h);
    cudaGetSymbolAddress((void**)&p_z,    g_zh);
    cudaGetSymbolAddress((void**)&p_h1,   g_h1h);
    cudaGetSymbolAddress((void**)&p_agg2, g_agg2h);
    cudaGetSymbolAddress((void**)&p_h2,   g_h2h);
    cudaGetSymbolAddress((void**)&p_sums, g_sums);
    cudaGetSymbolAddress((void**)&p_cnt,  g_cnt);
    cudaGetSymbolAddress((void**)&p_wh,   g_wh);
    cudaGetSymbolAddress((void**)&p_deg,  g_deg);
    cudaGetSymbolAddress((void**)&p_off,  g_off);
    cudaGetSymbolAddress((void**)&p_pos,  g_pos);
    cudaGetSymbolAddress((void**)&p_elist, g_elist);

    cudaFuncSetAttribute(gemm_fp16_kernel,
                         cudaFuncAttributeMaxDynamicSharedMemorySize,
                         GEMM_SMEM_BYTES);

    const dim3 gemmGrid(EMB / BN, (Nn + BM - 1) / BM);

    // 0) weight prep
    wprep_all_kernel<<<(WTOT + 255) / 256, 256>>>(g1w1, g1w2, g2w1, g2w2, p_wh);

    // 0b) CSR build
    zero_kernel<<<(Nn / 4 + 255) / 256, 256>>>((float4*)p_deg, Nn / 4);
    count_kernel<<<(Ee + 255) / 256, 256>>>(ei, p_deg);
    scan_kernel<<<1, 1024>>>(p_deg, p_off, p_pos, Nn);
    fill_kernel<<<(Ee + 255) / 256, 256>>>(ei, p_pos, p_elist);

    // 1) temporal conv stack -> h0
    conv_kernel<<<Nn, 256>>>(x, conv0_w, bn0_g, bn0_b, bn0_m, bn0_v,
                             conv1_w, conv2_w, bn2_g, bn2_b, bn2_m, bn2_v, p_h0);

    // 2) GIN1 aggregation
    gather_kernel<FIN><<<Nn, FIN / 8>>>(p_off, p_elist, p_h0, p_agg1);

    // 3) GIN1 MLP
    gemm_fp16_kernel<<<gemmGrid, 256, GEMM_SMEM_BYTES>>>(p_agg1, p_wh + WO1, g1b1, p_z, Nn, FIN, EMB, 1);
    gemm_fp16_kernel<<<gemmGrid, 256, GEMM_SMEM_BYTES>>>(p_z, p_wh + WO2, g1b2, p_h1, Nn, EMB, EMB, 1);

    // 4) GIN2 aggregation
    gather_kernel<EMB><<<Nn, EMB / 8>>>(p_off, p_elist, p_h1, p_agg2);

    // 5) GIN2 MLP
    gemm_fp16_kernel<<<gemmGrid, 256, GEMM_SMEM_BYTES>>>(p_agg2, p_wh + WO3, g2b1, p_z, Nn, EMB, EMB, 1);
    gemm_fp16_kernel<<<gemmGrid, 256, GEMM_SMEM_BYTES>>>(p_z, p_wh + WO4, g2b2, p_h2, Nn, EMB, EMB, 1);

    // 6) graph mean pool + dense + log_softmax
    {
        int n4s = Gg * EMB / 4;
        zero_kernel<<<(n4s + 255) / 256, 256>>>((float4*)p_sums, n4s);
        zero_kernel<<<1, 256>>>((float4*)p_cnt, Gg / 4);
        pool_kernel<<<Nn, EMB / 4>>>(batch, p_h2, p_sums, p_cnt);
        head_kernel<<<Gg, EMB / 4>>>(p_sums, p_cnt, dW, dB, out);
    }
}

// round 16
// speedup vs baseline: 1.2057x; 1.2057x over previous
#include <cuda_runtime.h>
#include <cuda_bf16.h>
#include <cuda_fp16.h>
#include <math.h>
#include <stdint.h>

#define Nn 20000
#define Tt 256
#define Ee 320000
#define Gg 64
#define CT 8
#define CP 16
#define EMB 768
#define OUTC 4
#define FIN 512
#define BN_EPS 1e-5f

// ---------------- scratch (device globals, no allocation) ----------------
__device__ __align__(16) __half g_h0h[(size_t)Nn * FIN];
__device__ __align__(16) __half g_agg1h[(size_t)Nn * FIN];
__device__ __align__(16) __half g_zh[(size_t)Nn * EMB];
__device__ __align__(16) __half g_h1h[(size_t)Nn * EMB];
__device__ __align__(16) __half g_agg2h[(size_t)Nn * EMB];
__device__ __align__(16) __half g_h2h[(size_t)Nn * EMB];
__device__ float g_sums[Gg * EMB];
__device__ float g_cnt[Gg];

// CSR scratch
__device__ int g_deg[Nn];
__device__ int g_off[Nn + 4];
__device__ int g_pos[Nn];
__device__ int g_elist[Ee];

// packed fp16x2 weight buffer: layout [K/2][M] uint32 (pair along k)
#define WO1 0
#define WO2 196608
#define WO3 491520
#define WO4 786432
#define WTOT 1081344
__device__ uint32_t g_wh[WTOT];

// ---------------- fused temporal conv + BN + pool (fp16 out) ----------------
// stage2 redesign: warp c owns channel c; thread handles 8 consecutive times,
// window read as 8x float4 from halo-padded s1s row (saves ~2x smem crossbar).
__global__ void __launch_bounds__(256) conv_kernel(
    const float* __restrict__ x,
    const float* __restrict__ w0,
    const float* __restrict__ g0, const float* __restrict__ b0,
    const float* __restrict__ m0, const float* __restrict__ v0,
    const float* __restrict__ w1,
    const float* __restrict__ w2,
    const float* __restrict__ g2, const float* __restrict__ b2,
    const float* __restrict__ m2, const float* __restrict__ v2,
    __half* __restrict__ hout)
{
    __shared__ float xs[256];
    __shared__ float w0s[264];
    __shared__ float w1s[168];
    __shared__ float w2s[128];
    __shared__ float sc0[8], sh0[8], sc2[16], sh2[16];
    __shared__ __align__(16) float s1s[8][288];  // [12 left halo | 256 | 20 right halo]
    __shared__ __align__(16) float s2s[8][264];

    const int t = threadIdx.x;
    const int n = blockIdx.x;

    xs[t] = x[(size_t)n * Tt + t];
    for (int i = t; i < 264; i += 256) w0s[i] = w0[i];
    if (t < 168) w1s[t] = w1[t];
    if (t < 128) w2s[t] = w2[t];
    if (t < 8)  { float s = g0[t] * rsqrtf(v0[t] + BN_EPS); sc0[t] = s; sh0[t] = b0[t] - m0[t] * s; }
    if (t < 16) { float s = g2[t] * rsqrtf(v2[t] + BN_EPS); sc2[t] = s; sh2[t] = b2[t] - m2[t] * s; }
    // zero halos of s1s
    if (t < 12) {
#pragma unroll
        for (int c = 0; c < 8; c++) s1s[c][t] = 0.f;
    } else if (t >= 236) {
#pragma unroll
        for (int c = 0; c < 8; c++) s1s[c][t + 32] = 0.f;  // 268..287
    }
    __syncthreads();

    // stage 1: conv0 (1->8, k=33, SAME) + bn0 -> s1s[c][12+t]
    {
        float acc[8];
#pragma unroll
        for (int c = 0; c < 8; c++) acc[c] = 0.f;
#pragma unroll
        for (int w = 0; w < 33; w++) {
            int tt = t + w - 16;
            float xv = (tt >= 0 && tt < 256) ? xs[tt] : 0.f;
#pragma unroll
            for (int c = 0; c < 8; c++) acc[c] += xv * w0s[w * 8 + c];
        }
#pragma unroll
        for (int c = 0; c < 8; c++) s1s[c][12 + t] = acc[c] * sc0[c] + sh0[c];
    }
    __syncthreads();

    // stage 2: depthwise conv (k=21, SAME) + relu.
    // warp c = t>>5 owns channel c; thread tb = t&31 computes times tb*8..tb*8+7.
    {
        const int c = t >> 5;
        const int tb = t & 31;
        float w1c[21];
#pragma unroll
        for (int w = 0; w < 21; w++) w1c[w] = w1s[w * 8 + c];  // broadcast within warp
        float win[32];  // covers times tb*8-12 .. tb*8+19
#pragma unroll
        for (int j = 0; j < 8; j++) {
            float4 v = *(const float4*)&s1s[c][tb * 8 + j * 4];
            win[j * 4 + 0] = v.x; win[j * 4 + 1] = v.y;
            win[j * 4 + 2] = v.z; win[j * 4 + 3] = v.w;
        }
        float o8[8];
#pragma unroll
        for (int k = 0; k < 8; k++) {
            float a = 0.f;
#pragma unroll
            for (int w = 0; w < 21; w++) a += win[k + w + 2] * w1c[w];
            o8[k] = fmaxf(a, 0.f);
        }
        *(float4*)&s2s[c][tb * 8]     = make_float4(o8[0], o8[1], o8[2], o8[3]);
        *(float4*)&s2s[c][tb * 8 + 4] = make_float4(o8[4], o8[5], o8[6], o8[7]);
    }
    __syncthreads();

    // stage 3: 1x1 conv (8->16) + bn2 + relu + mean-pool over 8 time steps
    {
        float s2r[8];
#pragma unroll
        for (int c = 0; c < 8; c++) s2r[c] = s2s[c][t];
        const int lane = t & 31;
#pragma unroll
        for (int o = 0; o < 16; o++) {
            float a = 0.f;
#pragma unroll
            for (int c = 0; c < 8; c++) a += s2r[c] * w2s[c * 16 + o];
            a = fmaxf(a * sc2[o] + sh2[o], 0.f);
            a += __shfl_xor_sync(0xffffffffu, a, 1);
            a += __shfl_xor_sync(0xffffffffu, a, 2);
            a += __shfl_xor_sync(0xffffffffu, a, 4);
            if ((lane & 7) == 0)
                hout[(size_t)n * FIN + (t >> 3) * 16 + o] = __float2half(a * 0.125f);
        }
    }
}

// ---------------- utility kernels ----------------
__global__ void zero_kernel(float4* __restrict__ p, int n4)
{
    int i = blockIdx.x * blockDim.x + threadIdx.x;
    int stride = gridDim.x * blockDim.x;
    float4 z = make_float4(0.f, 0.f, 0.f, 0.f);
    for (; i < n4; i += stride) p[i] = z;
}

// ---------------- weight prep: all 4 fp32 [K][M] -> packed fp16x2 [K/2][M] ----
__global__ void __launch_bounds__(256) wprep_all_kernel(
    const float* __restrict__ w1, const float* __restrict__ w2,
    const float* __restrict__ w3, const float* __restrict__ w4,
    uint32_t* __restrict__ Wh)
{
    int idx = blockIdx.x * blockDim.x + threadIdx.x;
    if (idx >= WTOT) return;
    const float* W;
    int local;
    if (idx < WO2)      { W = w1; local = idx; }
    else if (idx < WO3) { W = w2; local = idx - WO2; }
    else if (idx < WO4) { W = w3; local = idx - WO3; }
    else                { W = w4; local = idx - WO4; }
    int kp = local / EMB, n = local - kp * EMB;
    float f0 = W[(size_t)(2 * kp) * EMB + n];
    float f1 = W[(size_t)(2 * kp + 1) * EMB + n];
    __half2 h = __floats2half2_rn(f0, f1);
    Wh[idx] = *(uint32_t*)&h;
}

// ---------------- CSR build ----------------
__global__ void count_kernel(const int* __restrict__ ei, int* __restrict__ deg)
{
    int e = blockIdx.x * blockDim.x + threadIdx.x;
    if (e < Ee) atomicAdd(&deg[__ldg(ei + Ee + e)], 1);
}

// single-block hierarchical exclusive scan (round-12 version, coalesced)
__global__ void __launch_bounds__(1024) scan_kernel(
    const int* __restrict__ deg, int* __restrict__ off, int* __restrict__ pos, int n)
{
    __shared__ int wsum[32];
    __shared__ int sbase;
    const int tid = threadIdx.x, lane = tid & 31, wid = tid >> 5;
    if (tid == 0) sbase = 0;
    __syncthreads();
    for (int start = 0; start < n; start += 1024) {
        int idx = start + tid;
        int v = (idx < n) ? deg[idx] : 0;
        int x = v;
#pragma unroll
        for (int d = 1; d < 32; d <<= 1) {
            int y = __shfl_up_sync(0xffffffffu, x, d);
            if (lane >= d) x += y;
        }
        if (lane == 31) wsum[wid] = x;
        __syncthreads();
        if (wid == 0) {
            int w = wsum[lane];
#pragma unroll
            for (int d = 1; d < 32; d <<= 1) {
                int y = __shfl_up_sync(0xffffffffu, w, d);
                if (lane >= d) w += y;
            }
            wsum[lane] = w;
        }
        __syncthreads();
        int warpoff = (wid == 0) ? 0 : wsum[wid - 1];
        int excl = sbase + warpoff + x - v;
        if (idx < n) { off[idx] = excl; pos[idx] = excl; }
        int total = wsum[31];
        __syncthreads();
        if (tid == 0) sbase += total;
        __syncthreads();
    }
    if (tid == 0) off[n] = sbase;
}

__global__ void fill_kernel(const int* __restrict__ ei,
                            int* __restrict__ pos, int* __restrict__ elist)
{
    int e = blockIdx.x * blockDim.x + threadIdx.x;
    if (e < Ee) {
        int d = __ldg(ei + Ee + e);
        int p = atomicAdd(&pos[d], 1);
        elist[p] = __ldg(ei + e);
    }
}

// ---------------- CSR gather (fp16, fp32 accumulate; GPN nodes per block) -----
template <int F, int GPN>
__global__ void __launch_bounds__((F / 8) * GPN) gather_kernel(
    const int* __restrict__ off, const int* __restrict__ elist,
    const __half* __restrict__ h, __half* __restrict__ agg)
{
    const int tpn = F / 8;
    const int n = blockIdx.x * GPN + threadIdx.x / tpn;
    const int f = threadIdx.x % tpn;
    float a[8];
    {
        uint4 u = __ldg((const uint4*)(h + (size_t)n * F) + f);
        float2 p0 = __half22float2(*(__half2*)&u.x);
        float2 p1 = __half22float2(*(__half2*)&u.y);
        float2 p2 = __half22float2(*(__half2*)&u.z);
        float2 p3 = __half22float2(*(__half2*)&u.w);
        a[0] = p0.x; a[1] = p0.y; a[2] = p1.x; a[3] = p1.y;
        a[4] = p2.x; a[5] = p2.y; a[6] = p3.x; a[7] = p3.y;
    }
    int s = __ldg(off + n);
    const int e = __ldg(off + n + 1);
#define ACCUM(u) do { \
        float2 q; \
        q = __half22float2(*(__half2*)&(u).x); a[0] += q.x; a[1] += q.y; \
        q = __half22float2(*(__half2*)&(u).y); a[2] += q.x; a[3] += q.y; \
        q = __half22float2(*(__half2*)&(u).z); a[4] += q.x; a[5] += q.y; \
        q = __half22float2(*(__half2*)&(u).w); a[6] += q.x; a[7] += q.y; \
    } while (0)
    for (; s + 3 < e; s += 4) {
        int s0 = __ldg(elist + s);
        int s1 = __ldg(elist + s + 1);
        int s2 = __ldg(elist + s + 2);
        int s3 = __ldg(elist + s + 3);
        uint4 u0 = __ldg((const uint4*)(h + (size_t)s0 * F) + f);
        uint4 u1 = __ldg((const uint4*)(h + (size_t)s1 * F) + f);
        uint4 u2 = __ldg((const uint4*)(h + (size_t)s2 * F) + f);
        uint4 u3 = __ldg((const uint4*)(h + (size_t)s3 * F) + f);
        ACCUM(u0); ACCUM(u1); ACCUM(u2); ACCUM(u3);
    }
    for (; s < e; s++) {
        int s0 = __ldg(elist + s);
        uint4 u0 = __ldg((const uint4*)(h + (size_t)s0 * F) + f);
        ACCUM(u0);
    }
#undef ACCUM
    uint4 o;
    __half2 h0 = __floats2half2_rn(a[0], a[1]);
    __half2 h1 = __floats2half2_rn(a[2], a[3]);
    __half2 h2 = __floats2half2_rn(a[4], a[5]);
    __half2 h3 = __floats2half2_rn(a[6], a[7]);
    o.x = *(uint32_t*)&h0; o.y = *(uint32_t*)&h1;
    o.z = *(uint32_t*)&h2; o.w = *(uint32_t*)&h3;
    *((uint4*)(agg + (size_t)n * F) + f) = o;
}

// ---------------- fp16 GEMM (round-12 config): 128x128, cp.async x3 ----------
#define BM 128
#define BN 128
#define BK 32
#define KP 16
#define AS_STRIDE 20
#define BS_STRIDE 136
#define NSTAGE 3
#define AS_ELEMS (BM * AS_STRIDE)
#define BS_ELEMS (KP * BS_STRIDE)
#define GEMM_SMEM_BYTES ((NSTAGE * (AS_ELEMS + BS_ELEMS)) * 4)

__device__ __forceinline__ void cp_async16(uint32_t dst, const void* src, int sz)
{
    asm volatile("cp.async.cg.shared.global [%0], [%1], 16, %2;"
                 :: "r"(dst), "l"(src), "r"(sz));
}
__device__ __forceinline__ void cp_commit()
{
    asm volatile("cp.async.commit_group;");
}

__device__ __forceinline__ void mma_fp16(
    float* d, const uint32_t* a, uint32_t b0, uint32_t b1)
{
    asm volatile(
        "mma.sync.aligned.m16n8k16.row.col.f32.f16.f16.f32 "
        "{%0,%1,%2,%3}, {%4,%5,%6,%7}, {%8,%9}, {%0,%1,%2,%3};"
        : "+f"(d[0]), "+f"(d[1]), "+f"(d[2]), "+f"(d[3])
        : "r"(a[0]), "r"(a[1]), "r"(a[2]), "r"(a[3]), "r"(b0), "r"(b1));
}

__global__ void __launch_bounds__(256, 2) gemm_fp16_kernel(
    const __half* __restrict__ A,
    const uint32_t* __restrict__ Bh,
    const float* __restrict__ bias,
    __half* __restrict__ C, int Nrows, int K, int M, int doRelu)
{
    extern __shared__ uint32_t smem[];
    uint32_t* AsBase = smem;
    uint32_t* BsBase = smem + NSTAGE * AS_ELEMS;

    const int tid = threadIdx.x;
    const int lane = tid & 31;
    const int warp = tid >> 5;
    const int warp_m = warp & 3;
    const int warp_n = warp >> 2;
    const int rowBase = blockIdx.y * BM;
    const int colBase = blockIdx.x * BN;

    const int r0 = tid >> 2;
    const int c4 = tid & 3;
    const int kp0 = tid >> 5;
    const int n4 = tid & 31;

    int rowA0 = rowBase + r0, rowA1 = rowBase + r0 + 64;
    const int sz0 = (rowA0 < Nrows) ? 16 : 0;
    const int sz1 = (rowA1 < Nrows) ? 16 : 0;
    if (rowA0 >= Nrows) rowA0 = Nrows - 1;
    if (rowA1 >= Nrows) rowA1 = Nrows - 1;
    const __half* aSrc0 = A + (size_t)rowA0 * K + c4 * 8;
    const __half* aSrc1 = A + (size_t)rowA1 * K + c4 * 8;
    const uint32_t* bSrc0 = Bh + (size_t)kp0 * M + colBase + n4 * 4;
    const uint32_t* bSrc1 = Bh + (size_t)(kp0 + 8) * M + colBase + n4 * 4;

    uint32_t adst0[NSTAGE], adst1[NSTAGE], bdst0[NSTAGE], bdst1[NSTAGE];
#pragma unroll
    for (int b = 0; b < NSTAGE; b++) {
        adst0[b] = (uint32_t)__cvta_generic_to_shared(
            &AsBase[b * AS_ELEMS + r0 * AS_STRIDE + c4 * 4]);
        adst1[b] = (uint32_t)__cvta_generic_to_shared(
            &AsBase[b * AS_ELEMS + (r0 + 64) * AS_STRIDE + c4 * 4]);
        bdst0[b] = (uint32_t)__cvta_generic_to_shared(
            &BsBase[b * BS_ELEMS + kp0 * BS_STRIDE + n4 * 4]);
        bdst1[b] = (uint32_t)__cvta_generic_to_shared(
            &BsBase[b * BS_ELEMS + (kp0 + 8) * BS_STRIDE + n4 * 4]);
    }

    float acc[2][8][4];
#pragma unroll
    for (int i = 0; i < 2; i++)
#pragma unroll
        for (int j = 0; j < 8; j++)
#pragma unroll
            for (int r = 0; r < 4; r++) acc[i][j][r] = 0.f;

    const int nsteps = K / BK;

#define ISSUE(s) do { \
        int _b = (s) % NSTAGE; \
        cp_async16(adst0[_b], aSrc0 + (size_t)(s) * BK, sz0); \
        cp_async16(adst1[_b], aSrc1 + (size_t)(s) * BK, sz1); \
        cp_async16(bdst0[_b], bSrc0 + (size_t)(s) * KP * M, 16); \
        cp_async16(bdst1[_b], bSrc1 + (size_t)(s) * KP * M, 16); \
        cp_commit(); \
    } while (0)

    ISSUE(0);
    if (nsteps > 1) ISSUE(1);

    for (int s = 0; s < nsteps; s++) {
        if (s + 1 < nsteps) asm volatile("cp.async.wait_group 1;");
        else                asm volatile("cp.async.wait_group 0;");
        __syncthreads();
        if (s + 2 < nsteps) ISSUE(s + 2);

        const uint32_t* As = AsBase + (s % NSTAGE) * AS_ELEMS;
        const uint32_t* Bs = BsBase + (s % NSTAGE) * BS_ELEMS;

#pragma unroll
        for (int step = 0; step < 2; step++) {
            const int koff = step * 8;
            uint32_t a[2][4];
#pragma unroll
            for (int i = 0; i < 2; i++) {
                int mr = warp_m * 32 + i * 16 + (lane >> 2);
                int kc = koff + (lane & 3);
                a[i][0] = As[mr * AS_STRIDE + kc];
                a[i][1] = As[(mr + 8) * AS_STRIDE + kc];
                a[i][2] = As[mr * AS_STRIDE + kc + 4];
                a[i][3] = As[(mr + 8) * AS_STRIDE + kc + 4];
            }
#pragma unroll
            for (int j = 0; j < 8; j++) {
                int kb = koff + (lane & 3);
                int nb = warp_n * 64 + j * 8 + (lane >> 2);
                uint32_t b0 = Bs[kb * BS_STRIDE + nb];
                uint32_t b1 = Bs[(kb + 4) * BS_STRIDE + nb];
#pragma unroll
                for (int i = 0; i < 2; i++) {
                    mma_fp16(acc[i][j], a[i], b0, b1);
                }
            }
        }
    }
#undef ISSUE

#pragma unroll
    for (int i = 0; i < 2; i++) {
        int r = rowBase + warp_m * 32 + i * 16 + (lane >> 2);
#pragma unroll
        for (int j = 0; j < 8; j++) {
            int c0 = colBase + warp_n * 64 + j * 8 + (lane & 3) * 2;
            float b0v = bias[c0];
            float b1v = bias[c0 + 1];
            float v0 = acc[i][j][0] + b0v;
            float v1 = acc[i][j][1] + b1v;
            float v2 = acc[i][j][2] + b0v;
            float v3 = acc[i][j][3] + b1v;
            if (doRelu) {
                v0 = fmaxf(v0, 0.f); v1 = fmaxf(v1, 0.f);
                v2 = fmaxf(v2, 0.f); v3 = fmaxf(v3, 0.f);
            }
            if (r < Nrows) {
                __half2 p = __floats2half2_rn(v0, v1);
                *(uint32_t*)(C + (size_t)r * M + c0) = *(uint32_t*)&p;
            }
            if (r + 8 < Nrows) {
                __half2 p = __floats2half2_rn(v2, v3);
                *(uint32_t*)(C + (size_t)(r + 8) * M + c0) = *(uint32_t*)&p;
            }
        }
    }
}

// ---------------- graph mean-pool: sums/counts (fp16 in, red.v4) -------------
__global__ void __launch_bounds__(192) pool_kernel(
    const int* __restrict__ batch, const __half* __restrict__ h,
    float* __restrict__ sums, float* __restrict__ cnt)
{
    const int n = blockIdx.x;
    const int b = __ldg(batch + n);
    const int f = threadIdx.x;
    uint2 u = __ldg((const uint2*)(h + (size_t)n * EMB) + f);
    float2 p0 = __half22float2(*(__half2*)&u.x);
    float2 p1 = __half22float2(*(__half2*)&u.y);
    float* s = sums + (size_t)b * EMB + f * 4;
    asm volatile("red.global.add.v4.f32 [%0], {%1,%2,%3,%4};"
                 :: "l"(s), "f"(p0.x), "f"(p0.y), "f"(p1.x), "f"(p1.y) : "memory");
    if (f == 0) atomicAdd(&cnt[b], 1.0f);
}

// ---------------- head: mean, dense, log_softmax ----------------
__global__ void __launch_bounds__(192) head_kernel(
    const float* __restrict__ sums, const float* __restrict__ cnt,
    const float* __restrict__ W, const float* __restrict__ bias,
    float* __restrict__ out)
{
    __shared__ float red[192][4];
    const int g = blockIdx.x;
    const int t = threadIdx.x;
    const float c = fmaxf(cnt[g], 1.f);
    float4 p = *(const float4*)(sums + (size_t)g * EMB + t * 4);
    const float inv = 1.f / c;
    p.x *= inv; p.y *= inv; p.z *= inv; p.w *= inv;
    const int f = t * 4;
#pragma unroll
    for (int o = 0; o < 4; o++) {
        red[t][o] = p.x * W[(f + 0) * 4 + o] + p.y * W[(f + 1) * 4 + o] +
                    p.z * W[(f + 2) * 4 + o] + p.w * W[(f + 3) * 4 + o];
    }
    __syncthreads();
    if (t == 0) {
        float l[4];
#pragma unroll
        for (int o = 0; o < 4; o++) {
            float s = bias[o];
            for (int i = 0; i < 192; i++) s += red[i][o];
            l[o] = s;
        }
        float m = fmaxf(fmaxf(l[0], l[1]), fmaxf(l[2], l[3]));
        float se = expf(l[0] - m) + expf(l[1] - m) + expf(l[2] - m) + expf(l[3] - m);
        float lse = m + logf(se);
#pragma unroll
        for (int o = 0; o < 4; o++) out[g * 4 + o] = l[o] - lse;
    }
}

// ---------------- launch ----------------
extern "C" void kernel_launch(void* const* d_in, const int* in_sizes, int n_in,
                              void* d_out, int out_size)
{
    const float* x       = (const float*)d_in[0];
    const int*   ei      = (const int*)d_in[1];
    const int*   batch   = (const int*)d_in[2];
    const float* conv0_w = (const float*)d_in[3];
    const float* bn0_g   = (const float*)d_in[4];
    const float* bn0_b   = (const float*)d_in[5];
    const float* bn0_m   = (const float*)d_in[6];
    const float* bn0_v   = (const float*)d_in[7];
    const float* conv1_w = (const float*)d_in[8];
    const float* conv2_w = (const float*)d_in[9];
    const float* bn2_g   = (const float*)d_in[10];
    const float* bn2_b   = (const float*)d_in[11];
    const float* bn2_m   = (const float*)d_in[12];
    const float* bn2_v   = (const float*)d_in[13];
    const float* g1w1    = (const float*)d_in[14];
    const float* g1b1    = (const float*)d_in[15];
    const float* g1w2    = (const float*)d_in[16];
    const float* g1b2    = (const float*)d_in[17];
    const float* g2w1    = (const float*)d_in[18];
    const float* g2b1    = (const float*)d_in[19];
    const float* g2w2    = (const float*)d_in[20];
    const float* g2b2    = (const float*)d_in[21];
    const float* dW      = (const float*)d_in[22];
    const float* dB      = (const float*)d_in[23];
    float* out = (float*)d_out;

    __half *p_h0, *p_agg1, *p_z, *p_h1, *p_agg2, *p_h2;
    float *p_sums, *p_cnt;
    uint32_t *p_wh;
    int *p_deg, *p_off, *p_pos, *p_elist;
    cudaGetSymbolAddress((void**)&p_h0,   g_h0h);
    cudaGetSymbolAddress((void**)&p_agg1, g_agg1h);
    cudaGetSymbolAddress((void**)&p_z,    g_zh);
    cudaGetSymbolAddress((void**)&p_h1,   g_h1h);
    cudaGetSymbolAddress((void**)&p_agg2, g_agg2h);
    cudaGetSymbolAddress((void**)&p_h2,   g_h2h);
    cudaGetSymbolAddress((void**)&p_sums, g_sums);
    cudaGetSymbolAddress((void**)&p_cnt,  g_cnt);
    cudaGetSymbolAddress((void**)&p_wh,   g_wh);
    cudaGetSymbolAddress((void**)&p_deg,  g_deg);
    cudaGetSymbolAddress((void**)&p_off,  g_off);
    cudaGetSymbolAddress((void**)&p_pos,  g_pos);
    cudaGetSymbolAddress((void**)&p_elist, g_elist);

    cudaFuncSetAttribute(gemm_fp16_kernel,
                         cudaFuncAttributeMaxDynamicSharedMemorySize,
                         GEMM_SMEM_BYTES);

    const dim3 gemmGrid(EMB / BN, (Nn + BM - 1) / BM);

    // 0) weight prep
    wprep_all_kernel<<<(WTOT + 255) / 256, 256>>>(g1w1, g1w2, g2w1, g2w2, p_wh);

    // 0b) CSR build
    zero_kernel<<<(Nn / 4 + 255) / 256, 256>>>((float4*)p_deg, Nn / 4);
    count_kernel<<<(Ee + 255) / 256, 256>>>(ei, p_deg);
    scan_kernel<<<1, 1024>>>(p_deg, p_off, p_pos, Nn);
    fill_kernel<<<(Ee + 255) / 256, 256>>>(ei, p_pos, p_elist);

    // 1) temporal conv stack -> h0
    conv_kernel<<<Nn, 256>>>(x, conv0_w, bn0_g, bn0_b, bn0_m, bn0_v,
                             conv1_w, conv2_w, bn2_g, bn2_b, bn2_m, bn2_v, p_h0);

    // 2) GIN1 aggregation (4 nodes per 256-thread block)
    gather_kernel<FIN, 4><<<Nn / 4, 256>>>(p_off, p_elist, p_h0, p_agg1);

    // 3) GIN1 MLP
    gemm_fp16_kernel<<<gemmGrid, 256, GEMM_SMEM_BYTES>>>(p_agg1, p_wh + WO1, g1b1, p_z, Nn, FIN, EMB, 1);
    gemm_fp16_kernel<<<gemmGrid, 256, GEMM_SMEM_BYTES>>>(p_z, p_wh + WO2, g1b2, p_h1, Nn, EMB, EMB, 1);

    // 4) GIN2 aggregation (2 nodes per 192-thread block)
    gather_kernel<EMB, 2><<<Nn / 2, 192>>>(p_off, p_elist, p_h1, p_agg2);

    // 5) GIN2 MLP
    gemm_fp16_kernel<<<gemmGrid, 256, GEMM_SMEM_BYTES>>>(p_agg2, p_wh + WO3, g2b1, p_z, Nn, EMB, EMB, 1);
    gemm_fp16_kernel<<<gemmGrid, 256, GEMM_SMEM_BYTES>>>(p_z, p_wh + WO4, g2b2, p_h2, Nn, EMB, EMB, 1);

    // 6) graph mean pool + dense + log_softmax
    {
        int n4s = Gg * EMB / 4;
        zero_kernel<<<(n4s + 255) / 256, 256>>>((float4*)p_sums, n4s);
        zero_kernel<<<1, 256>>>((float4*)p_cnt, Gg / 4);
        pool_kernel<<<Nn, EMB / 4>>>(batch, p_h2, p_sums, p_cnt);
        head_kernel<<<Gg, EMB / 4>>>(p_sums, p_cnt, dW, dB, out);
    }
}